// round 12
// baseline (speedup 1.0000x reference)
#include <cuda_runtime.h>
#include <cstdint>
#include <math.h>

#define TOKENS 16384
#define KDIM   2048
#define NEXP   64
#define TM     64                      // tokens per CTA -> grid 256
#define KC     64                      // K elems per chunk
#define NCHUNK (KDIM / KC)             // 32
#define SA     144                     // A smem row stride bytes (conflict-free ldmatrix)
#define STAGE  (64 * SA)               // 9216 per stage (A only)
#define DYN_SMEM (2 * STAGE)           // 18432, double-buffered
#define RESCUE_TH 2.5e-3f

typedef unsigned int u32;

// W pre-swizzled into m16n8k16 B-fragment layout (fp16 pairs), refreshed every call.
// u32 index p = (((c*4 + ks)*4 + np)*32 + lane)*4 + q
//   q: 0=b0 (n-tile even), 1=b1 (even), 2=b0 (odd), 3=b1 (odd)
//   n = np*16 + (q>>1)*8 + lane/4 ; k = c*64 + ks*16 + (q&1)*8 + (lane%4)*2 (+0,+1 packed lo,hi)
__device__ __align__(16) u32 g_Bf[NEXP * KDIM / 2];

// ---------------- helpers ----------------
static __device__ __forceinline__ u32 smem_u32(const void* p) {
    u32 a;
    asm("{ .reg .u64 t; cvta.to.shared.u64 t, %1; cvt.u32.u64 %0, t; }" : "=r"(a) : "l"(p));
    return a;
}
// pack two f32 -> f16x2 (low half = f0)
static __device__ __forceinline__ u32 cvt_h2(float f0, float f1) {
    u32 r;
    asm("cvt.rn.f16x2.f32 %0, %1, %2;" : "=r"(r) : "f"(f1), "f"(f0));
    return r;
}
static __device__ __forceinline__ void sts128(u32 a, u32 v0, u32 v1, u32 v2, u32 v3) {
    asm volatile("st.shared.v4.b32 [%0], {%1,%2,%3,%4};"
                 :: "r"(a), "r"(v0), "r"(v1), "r"(v2), "r"(v3) : "memory");
}
static __device__ __forceinline__ void ldm_x4(u32* r, u32 a) {
    asm volatile("ldmatrix.sync.aligned.m8n8.x4.shared.b16 {%0,%1,%2,%3}, [%4];"
                 : "=r"(r[0]), "=r"(r[1]), "=r"(r[2]), "=r"(r[3]) : "r"(a));
}
static __device__ __forceinline__ void mma_f16(float* c, const u32* a, u32 b0, u32 b1) {
    asm volatile("mma.sync.aligned.m16n8k16.row.col.f32.f16.f16.f32 "
                 "{%0,%1,%2,%3}, {%4,%5,%6,%7}, {%8,%9}, {%0,%1,%2,%3};"
                 : "+f"(c[0]), "+f"(c[1]), "+f"(c[2]), "+f"(c[3])
                 : "r"(a[0]), "r"(a[1]), "r"(a[2]), "r"(a[3]), "r"(b0), "r"(b1));
}

// ---------------- W -> B-fragment prep kernel (65536 threads, one u32 each) ----
__global__ void prep_bf(const float* __restrict__ W) {
    int p = blockIdx.x * blockDim.x + threadIdx.x;
    int q    = p & 3;
    int lane = (p >> 2) & 31;
    int np   = (p >> 7) & 3;
    int ks   = (p >> 9) & 3;
    int c    = p >> 11;
    int n = np * 16 + ((q >> 1) << 3) + (lane >> 2);
    int k = c * 64 + ks * 16 + ((q & 1) << 3) + ((lane & 3) << 1);
    const float* wr = W + (size_t)n * KDIM + k;
    g_Bf[p] = cvt_h2(wr[0], wr[1]);
}

// ---------------- warp-cooperative exact fp32 dot ----------------
static __device__ __forceinline__ float warp_dot(const float4* __restrict__ xr4,
                                                 const float4* __restrict__ wr4,
                                                 int lane) {
    float a0 = 0.f, a1 = 0.f, a2 = 0.f, a3 = 0.f;
#pragma unroll
    for (int i = 0; i < 16; i++) {
        float4 xv = __ldg(xr4 + lane + 32 * i);
        float4 wv = __ldg(wr4 + lane + 32 * i);
        a0 = fmaf(xv.x, wv.x, a0);
        a1 = fmaf(xv.y, wv.y, a1);
        a2 = fmaf(xv.z, wv.z, a2);
        a3 = fmaf(xv.w, wv.w, a3);
    }
    float s = (a0 + a1) + (a2 + a3);
#pragma unroll
    for (int o = 16; o > 0; o >>= 1)
        s += __shfl_xor_sync(0xffffffffu, s, o);
    return s;
}

// ---------------- main kernel ----------------
__global__ __launch_bounds__(256, 2)
void router_mma(const float* __restrict__ x,
                const float* __restrict__ W,
                const float* __restrict__ bias,
                float* __restrict__ out)
{
    extern __shared__ __align__(16) char dsmp[];
    const u32 sb = smem_u32(dsmp);
    __shared__ float s_bias[NEXP];
    __shared__ int   s_cnt;
    __shared__ int   s_list[TM];
    __shared__ float s_thr[TM];

    const int tid  = threadIdx.x;
    const int wid  = tid >> 5;
    const int lane = tid & 31;
    const int wm   = wid & 1;          // M block (32 tokens)
    const int wn   = wid >> 1;         // expert group np (16 experts)
    const int tokBase = blockIdx.x * TM;

    if (tid < NEXP) s_bias[tid] = bias[tid];
    if (tid == 0) s_cnt = 0;

    float acc[2][2][4];
#pragma unroll
    for (int i = 0; i < 2; i++)
#pragma unroll
        for (int j = 0; j < 2; j++)
#pragma unroll
            for (int q = 0; q < 4; q++) acc[i][j][q] = 0.f;

    float4 px0[4], px1[4];             // x ping-pong (chunk parity), lookahead 3
    uint4  bf0[4], bf1[4];             // B fragments ping-pong (chunk parity)
    const float4* xp  = (const float4*)x;
    const uint4*  bfp = (const uint4*)g_Bf;

    // x mapping: rows xrow & xrow+32, 2 consecutive float4 each (16B-aligned pairs)
    const int xrow = tid >> 3, xc8 = tid & 7;

#define LOAD_PX(P, c)                                                               \
    do {                                                                            \
        _Pragma("unroll")                                                           \
        for (int r = 0; r < 2; r++) {                                               \
            const float4* src = xp + (size_t)(tokBase + xrow + 32 * r) * (KDIM / 4) \
                                   + (c) * 16 + xc8 * 2;                            \
            P[2 * r]     = src[0];                                                  \
            P[2 * r + 1] = src[1];                                                  \
        }                                                                           \
    } while (0)

#define LDGB(BF, c)                                                                 \
    do {                                                                            \
        _Pragma("unroll")                                                           \
        for (int ks = 0; ks < 4; ks++)                                              \
            BF[ks] = bfp[(((c) * 4 + ks) * 4 + wn) * 32 + lane];                    \
    } while (0)

#define STS_A(P, st)                                                                \
    do {                                                                            \
        _Pragma("unroll")                                                           \
        for (int r = 0; r < 2; r++) {                                               \
            u32 a = sb + (u32)(st) * STAGE + (u32)((xrow + 32 * r) * SA + xc8 * 16);\
            float4 v0 = P[2 * r], v1 = P[2 * r + 1];                                \
            sts128(a, cvt_h2(v0.x, v0.y), cvt_h2(v0.z, v0.w),                       \
                      cvt_h2(v1.x, v1.y), cvt_h2(v1.z, v1.w));                      \
        }                                                                           \
    } while (0)

    // A ldmatrix base offset (stage-relative); verified mapping from R4
    const u32 aOff = (u32)((wm * 32 + (lane & 15)) * SA + (lane >> 4) * 16);

#define COMPUTE(st, BF)                                                             \
    do {                                                                            \
        const u32 aAddr = sb + (u32)(st) * STAGE + aOff;                            \
        _Pragma("unroll")                                                           \
        for (int ks = 0; ks < 4; ks++) {                                            \
            u32 A[2][4];                                                            \
            ldm_x4(A[0], aAddr + ks * 32);                                          \
            ldm_x4(A[1], aAddr + 16 * SA + ks * 32);                                \
            _Pragma("unroll")                                                       \
            for (int mt = 0; mt < 2; mt++) {                                        \
                mma_f16(acc[mt][0], A[mt], BF[ks].x, BF[ks].y);                     \
                mma_f16(acc[mt][1], A[mt], BF[ks].z, BF[ks].w);                     \
            }                                                                       \
        }                                                                           \
    } while (0)

    // ---------------- prologue ----------------
    LOAD_PX(px0, 0);
    LOAD_PX(px1, 1);
    LDGB(bf0, 0);
    STS_A(px0, 0);                 // waits on px0 DRAM latency once
    LOAD_PX(px0, 2);

    // ---------------- main loop ----------------
#pragma unroll 2
    for (int c = 0; c < NCHUNK; c++) {
        const int cur = c & 1, nxt = cur ^ 1;
        __syncthreads();           // A(c) in stage cur visible to all; stage nxt free

        if (c + 1 < NCHUNK) {
            if (nxt) {
                LDGB(bf1, c + 1);
                STS_A(px1, nxt);
            } else {
                LDGB(bf0, c + 1);
                STS_A(px0, nxt);
            }
        }
        if (c + 3 < NCHUNK) {
            if ((c + 3) & 1) {
                LOAD_PX(px1, c + 3);
            } else {
                LOAD_PX(px0, c + 3);
            }
        }

        if (cur) {
            COMPUTE(1, bf1);
        } else {
            COMPUTE(0, bf0);
        }
    }

    // ---------------- epilogue ----------------
    __syncthreads();
    float* ls = (float*)dsmp;            // logits staging [64][65] = 16.6KB <= 18.4KB
#pragma unroll
    for (int mt = 0; mt < 2; mt++)
#pragma unroll
        for (int nt = 0; nt < 2; nt++) {
            const int row = wm * 32 + mt * 16 + (lane >> 2);
            const int col = wn * 16 + nt * 8 + (lane & 3) * 2;
            ls[row * 65 + col]           = acc[mt][nt][0] + s_bias[col];
            ls[row * 65 + col + 1]       = acc[mt][nt][1] + s_bias[col + 1];
            ls[(row + 8) * 65 + col]     = acc[mt][nt][2] + s_bias[col];
            ls[(row + 8) * 65 + col + 1] = acc[mt][nt][3] + s_bias[col + 1];
        }
    __syncthreads();

    float* probs_out  = out;
    float* idx_out    = out + (size_t)TOKENS * 2;
    float* logits_out = out + (size_t)TOKENS * 4;

    // coalesced logits store: 1024 float4 per block, 4 per thread
#pragma unroll
    for (int r = 0; r < 4; r++) {
        int s  = tid + 256 * r;
        int t  = s >> 4;
        int e4 = s & 15;
        const float* lr = &ls[t * 65 + e4 * 4];
        *(float4*)(logits_out + (size_t)(tokBase + t) * NEXP + e4 * 4) =
            make_float4(lr[0], lr[1], lr[2], lr[3]);
    }

    // per-token top-2; near-ties enqueued for warp-parallel exact rescue
    if (tid < TM) {
        const int t = tid;
        const int gt = tokBase + t;
        const float* lr = &ls[t * 65];
        float m1 = -INFINITY, m2 = -INFINITY, m3 = -INFINITY;
        int i1 = 0, i2 = 0;
#pragma unroll
        for (int e = 0; e < NEXP; e++) {
            const float v = lr[e];
            if (v > m1)      { m3 = m2; m2 = m1; i2 = i1; m1 = v; i1 = e; }
            else if (v > m2) { m3 = m2; m2 = v; i2 = e; }
            else if (v > m3) { m3 = v; }
        }

        if ((m1 - m2 < RESCUE_TH) || (m2 - m3 < RESCUE_TH)) {
            int j = atomicAdd(&s_cnt, 1);
            s_list[j] = t;
            s_thr[t]  = m2 - RESCUE_TH;
        } else {
            const float ex2 = expf(m2 - m1);
            const float inv = 1.0f / (1.0f + ex2);
            probs_out[gt * 2 + 0] = inv;
            probs_out[gt * 2 + 1] = ex2 * inv;
            idx_out[gt * 2 + 0] = (float)i1;
            idx_out[gt * 2 + 1] = (float)i2;
        }
    }
    __syncthreads();

    // warp-parallel exact rescue
    const int cnt = s_cnt;
    for (int j = wid; j < cnt; j += 8) {
        const int t  = s_list[j];
        const int gt = tokBase + t;
        const float thr = s_thr[t];
        const float* lr = &ls[t * 65];
        const float4* xr4 = (const float4*)(x + (size_t)gt * KDIM);

        float e1 = -INFINITY, e2 = -INFINITY;
        int j1 = 0, j2 = 0;
        for (int e = 0; e < NEXP; e++) {          // ascending: jax first-index tie-break
            if (lr[e] > thr) {
                const float4* wr4 = (const float4*)(W + (size_t)e * KDIM);
                float ex = warp_dot(xr4, wr4, lane) + s_bias[e];
                if (ex > e1)      { e2 = e1; j2 = j1; e1 = ex; j1 = e; }
                else if (ex > e2) { e2 = ex; j2 = e; }
            }
        }
        if (lane == 0) {
            const float ex2 = expf(e2 - e1);
            const float inv = 1.0f / (1.0f + ex2);
            probs_out[gt * 2 + 0] = inv;
            probs_out[gt * 2 + 1] = ex2 * inv;
            idx_out[gt * 2 + 0] = (float)j1;
            idx_out[gt * 2 + 1] = (float)j2;
        }
    }
}

extern "C" void kernel_launch(void* const* d_in, const int* in_sizes, int n_in,
                              void* d_out, int out_size)
{
    const float* x = (const float*)d_in[0];
    const float* W = (const float*)d_in[1];
    const float* b = (const float*)d_in[2];
    float* out = (float*)d_out;

    cudaFuncSetAttribute(router_mma, cudaFuncAttributeMaxDynamicSharedMemorySize, DYN_SMEM);
    prep_bf<<<256, 256>>>(W);
    router_mma<<<TOKENS / TM, 256, DYN_SMEM>>>(x, W, b, out);
}